// round 9
// baseline (speedup 1.0000x reference)
#include <cuda_runtime.h>
#include <math.h>

#define TOKENS   16384
#define NEXP     256
#define HID      7168
#define NGROUP   8
#define TOPKG    4
#define TOPKN    8

// Scratch logits [T, E] (16 MB).
__device__ float g_logits[TOKENS * NEXP];

// ---------------------------------------------------------------------------
// Kernel 1: fp32 router GEMM with EIGEN-FAITHFUL ACCUMULATION ASSOCIATION.
//   C[t][e] = fold_panels( serial_fma_chain over kc-slice ), kc = 248
//   (Eigen gebp: aarch64 default L1=16KB -> k_cache=(16384-192)/64=253 -> 248;
//    panels ascending; C = ((0+S1)+S2)+... with separate f32 adds.)
// BM=128, BN=128, BK=8, 512 threads, 8x4 outputs/thread (needs 2 acc sets).
// ---------------------------------------------------------------------------
#define BM 128
#define BN 128
#define BK 8
#define KC_TILES 31   // 31 * BK = 248 = Eigen kc
#define SPAD 4

__global__ __launch_bounds__(512, 1) void router_gemm(
    const float* __restrict__ A,   // [T, H]
    const float* __restrict__ B,   // [E, H]
    float* __restrict__ C,         // [T, E]
    int T, int H, int E)
{
    __shared__ float As[BK][BM + SPAD];
    __shared__ float Bs[BK][BN + SPAD];

    const int tile_m = blockIdx.y * BM;
    const int tile_n = blockIdx.x * BN;
    const int tid = threadIdx.x;
    const int tx = tid & 31;        // col quad: 32 quads * 4 = 128
    const int ty = tid >> 5;        // row octet: 16 octets * 8 = 128

    float acc_tot[8][4];
    float acc_pan[8][4];
    #pragma unroll
    for (int i = 0; i < 8; i++)
        #pragma unroll
        for (int j = 0; j < 4; j++) { acc_tot[i][j] = 0.0f; acc_pan[i][j] = 0.0f; }

    const float* Ab = A + (size_t)tile_m * H;
    const float* Bb = B + (size_t)tile_n * H;

    const int l_row = tid >> 2;          // 0..127
    const int l_c2  = (tid & 3) * 2;     // 0,2,4,6

    const int ntiles = H / BK;           // 896
    int tile_in_panel = 0;

    for (int t = 0; t < ntiles; t++) {
        int k0 = t * BK;
        // Load A tile 128x8 (transposed into As[k][row]); 512 thr * 2 elems
        {
            float2 v = *reinterpret_cast<const float2*>(Ab + (size_t)l_row * H + k0 + l_c2);
            As[l_c2 + 0][l_row] = v.x;
            As[l_c2 + 1][l_row] = v.y;
        }
        {
            float2 v = *reinterpret_cast<const float2*>(Bb + (size_t)l_row * H + k0 + l_c2);
            Bs[l_c2 + 0][l_row] = v.x;
            Bs[l_c2 + 1][l_row] = v.y;
        }
        __syncthreads();

        #pragma unroll
        for (int k = 0; k < BK; k++) {
            float a[8], b[4];
            #pragma unroll
            for (int i = 0; i < 8; i++) a[i] = As[k][ty * 8 + i];
            #pragma unroll
            for (int j = 0; j < 4; j++) b[j] = Bs[k][tx * 4 + j];
            #pragma unroll
            for (int i = 0; i < 8; i++)
                #pragma unroll
                for (int j = 0; j < 4; j++)
                    acc_pan[i][j] = fmaf(a[i], b[j], acc_pan[i][j]);
        }
        __syncthreads();

        // Panel boundary: fold panel sum into total (separate f32 add),
        // exactly like Eigen's C += gebp(panel).
        if (++tile_in_panel == KC_TILES) {
            tile_in_panel = 0;
            #pragma unroll
            for (int i = 0; i < 8; i++)
                #pragma unroll
                for (int j = 0; j < 4; j++) {
                    acc_tot[i][j] = __fadd_rn(acc_tot[i][j], acc_pan[i][j]);
                    acc_pan[i][j] = 0.0f;
                }
        }
    }
    // Remainder panel (224 k's)
    #pragma unroll
    for (int i = 0; i < 8; i++)
        #pragma unroll
        for (int j = 0; j < 4; j++)
            acc_tot[i][j] = __fadd_rn(acc_tot[i][j], acc_pan[i][j]);

    #pragma unroll
    for (int i = 0; i < 8; i++) {
        int row = tile_m + ty * 8 + i;
        #pragma unroll
        for (int j = 0; j < 4; j++)
            C[(size_t)row * E + tile_n + tx * 4 + j] = acc_tot[i][j];
    }
}

// ---------------------------------------------------------------------------
// XLA:CPU fused-loop sigmoid: logistic_expander -> 1/(1+exp(-x)); exp via
// VF32Exp (Cephes), with FUSED n = floor(fma(x, log2e, 0.5)) (LLVM fmuladd).
// ---------------------------------------------------------------------------
__device__ __forceinline__ float vf32_exp(float x) {
    x = fminf(fmaxf(x, -87.8f), 88.8f);
    float fx = floorf(__fmaf_rn(x, 1.44269504088896341f, 0.5f));
    float tmp = __fmul_rn(fx, 0.693359375f);
    float z   = __fmul_rn(fx, -2.12194440e-4f);
    float r = __fsub_rn(__fsub_rn(x, tmp), z);
    float r2 = __fmul_rn(r, r);
    float y = 1.9875691500e-4f;
    y = __fmaf_rn(y, r, 1.3981999507e-3f);
    y = __fmaf_rn(y, r, 8.3334519073e-3f);
    y = __fmaf_rn(y, r, 4.1665795894e-2f);
    y = __fmaf_rn(y, r, 1.6666665459e-1f);
    y = __fmaf_rn(y, r, 5.0000001201e-1f);
    y = __fmaf_rn(y, r2, r);
    y = __fadd_rn(y, 1.0f);
    int n = (int)fx;
    return __fmul_rn(y, __int_as_float((n + 127) << 23));
}

__device__ __forceinline__ float xla_cpu_sigmoid(float x) {
    float e = vf32_exp(-x);
    return __fdiv_rn(1.0f, __fadd_rn(1.0f, e));
}

// ---------------------------------------------------------------------------
// Kernel 2: routing. One block (256 threads) per token.
// ---------------------------------------------------------------------------
__global__ __launch_bounds__(256) void router_topk(
    const float* __restrict__ logits,
    const float* __restrict__ bias,
    float* __restrict__ out_idx,
    float* __restrict__ out_w)
{
    __shared__ float s_score[NEXP];
    __shared__ float s_masked[NEXP];
    __shared__ float s_gscore[NGROUP];
    __shared__ int   s_gmask[NGROUP];
    __shared__ int   s_sel[TOPKN];

    const int t = blockIdx.x;
    const int e = threadIdx.x;
    const int warp = e >> 5, lane = e & 31;

    float logit = logits[(size_t)t * NEXP + e];
    float score = xla_cpu_sigmoid(logit);
    float corr = __fadd_rn(score, bias[e]);
    s_score[e] = score;

    // group top-2 sum (warp == group)
    float m1 = corr;
    #pragma unroll
    for (int o = 16; o > 0; o >>= 1)
        m1 = fmaxf(m1, __shfl_xor_sync(0xffffffffu, m1, o));
    unsigned ball = __ballot_sync(0xffffffffu, corr == m1);
    int firstlane = __ffs(ball) - 1;
    float v2 = (lane == firstlane) ? -INFINITY : corr;
    float m2 = v2;
    #pragma unroll
    for (int o = 16; o > 0; o >>= 1)
        m2 = fmaxf(m2, __shfl_xor_sync(0xffffffffu, m2, o));
    if (lane == 0) s_gscore[warp] = __fadd_rn(m1, m2);
    __syncthreads();

    // top-4 groups, stable (lowest index on ties)
    if (e == 0) {
        bool used[NGROUP];
        #pragma unroll
        for (int g = 0; g < NGROUP; g++) used[g] = false;
        for (int it = 0; it < TOPKG; it++) {
            float best = -INFINITY; int bi = 0;
            for (int g = 0; g < NGROUP; g++)
                if (!used[g] && s_gscore[g] > best) { best = s_gscore[g]; bi = g; }
            used[bi] = true;
        }
        #pragma unroll
        for (int g = 0; g < NGROUP; g++) s_gmask[g] = used[g] ? 1 : 0;
    }
    __syncthreads();

    s_masked[e] = s_gmask[warp] ? corr : 0.0f;
    __syncthreads();

    // top-8 over 256 (warp 0), stable
    if (warp == 0) {
        float lv[8];
        #pragma unroll
        for (int i = 0; i < 8; i++) lv[i] = s_masked[lane + i * 32];

        for (int it = 0; it < TOPKN; it++) {
            float best = -INFINITY; int bslot = 0;
            #pragma unroll
            for (int i = 0; i < 8; i++)
                if (lv[i] > best) { best = lv[i]; bslot = i; }
            int bidx = bslot * 32 + lane;
            #pragma unroll
            for (int o = 16; o > 0; o >>= 1) {
                float ov = __shfl_xor_sync(0xffffffffu, best, o);
                int   oi = __shfl_xor_sync(0xffffffffu, bidx, o);
                if (ov > best || (ov == best && oi < bidx)) { best = ov; bidx = oi; }
            }
            if (lane == 0) s_sel[it] = bidx;
            if (lane == (bidx & 31)) lv[bidx >> 5] = -INFINITY;
        }
        __syncwarp();

        float w = 0.0f;
        int myidx = 0;
        if (lane < TOPKN) {
            myidx = s_sel[lane];
            w = s_score[myidx];
        }
        float ws = w;
        #pragma unroll
        for (int o = 16; o > 0; o >>= 1)
            ws += __shfl_xor_sync(0xffffffffu, ws, o);
        if (lane < TOPKN) {
            float wn = __fmul_rn(__fdiv_rn(w, __fadd_rn(ws, 1e-20f)), 2.5f);
            out_idx[(size_t)t * TOPKN + lane] = (float)myidx;
            out_w[(size_t)t * TOPKN + lane] = wn;
        }
    }
}

// ---------------------------------------------------------------------------
extern "C" void kernel_launch(void* const* d_in, const int* in_sizes, int n_in,
                              void* d_out, int out_size) {
    const float* hidden = (const float*)d_in[0];
    const float* weight = (const float*)d_in[1];
    const float* bias   = (const float*)d_in[2];

    int E = in_sizes[2];
    int H = in_sizes[1] / E;
    int T = in_sizes[0] / H;

    float* logits = nullptr;
    cudaGetSymbolAddress((void**)&logits, g_logits);

    dim3 gemm_grid(E / BN, T / BM);
    router_gemm<<<gemm_grid, 512>>>(hidden, weight, logits, T, H, E);

    float* out = (float*)d_out;
    router_topk<<<T, 256>>>(logits, bias, out, out + (size_t)T * TOPKN);
}

// round 10
// speedup vs baseline: 2.1777x; 2.1777x over previous
#include <cuda_runtime.h>
#include <math.h>

#define TOKENS   16384
#define NEXP     256
#define HID      7168
#define NGROUP   8
#define TOPKG    4
#define TOPKN    8

// Scratch logits [T, E] (16 MB).
__device__ float g_logits[TOKENS * NEXP];

// ---------------------------------------------------------------------------
// Kernel 1: fp32 router GEMM, EIGEN-FAITHFUL ASSOCIATION (FROZEN NUMERICS):
//   per output: serial ascending-k fmaf chain within kc=248 panels,
//   C = ((0+S1)+S2)+... with separate __fadd_rn folds, remainder 224 last.
// Perf shape: BM=BN=128, BK=16 (2 sub-tiles of 8), 256 threads, 8x8/thread.
// acc_pan in regs (64); acc_tot in smem [64][256] (touched only at folds).
// Double-buffered smem tiles, one __syncthreads per 16 k.
// ---------------------------------------------------------------------------
#define BM 128
#define BN 128
#define BK 16
#define KC  248
#define TPAD 4               // tile row pad (floats)
#define TROW (BM + TPAD)     // 132
#define TILE_F (BK * TROW)   // floats per tile buffer (2112)

// dynamic smem layout (floats):
//   As[2][BK][TROW]  : 2*2112
//   Bs[2][BK][TROW]  : 2*2112
//   tot[64][256]     : 16384
#define SM_AS    0
#define SM_BS    (2 * TILE_F)
#define SM_TOT   (4 * TILE_F)
#define SM_TOTAL ((4 * TILE_F + 64 * 256) * 4)   // bytes = 99328

__global__ __launch_bounds__(256, 2) void router_gemm(
    const float* __restrict__ A,   // [T, H]
    const float* __restrict__ B,   // [E, H]
    float* __restrict__ C,         // [T, E]
    int T, int H, int E)
{
    extern __shared__ float sm[];
    float* sAs = sm + SM_AS;
    float* sBs = sm + SM_BS;
    float* sTot = sm + SM_TOT;

    const int tid = threadIdx.x;
    const int tx = tid & 15;         // expert octet 0..15
    const int ty = tid >> 4;         // token octet 0..15
    const int tile_m = blockIdx.y * BM;
    const int tile_n = blockIdx.x * BN;

    // loader mapping: 256 threads cover 128 rows x 16 cols (2 float4 each)
    const int lrow = tid >> 1;             // 0..127
    const int lcol = (tid & 1) * 8;        // 0 or 8

    const float* Ab = A + (size_t)(tile_m + lrow) * H + lcol;
    const float* Bb = B + (size_t)(tile_n + lrow) * H + lcol;

    // init tot = 0 (each thread owns column tid of 64 rows; conflict-free)
    #pragma unroll
    for (int i = 0; i < 64; i++) sTot[i * 256 + tid] = 0.0f;

    float acc[8][8];
    #pragma unroll
    for (int i = 0; i < 8; i++)
        #pragma unroll
        for (int j = 0; j < 8; j++) acc[i][j] = 0.0f;

    const int NIT = H / BK;   // 448

    // ---- preload tile 0 into buffer 0 ----
    {
        float4 a0 = *reinterpret_cast<const float4*>(Ab + 0);
        float4 a1 = *reinterpret_cast<const float4*>(Ab + 4);
        float4 b0 = *reinterpret_cast<const float4*>(Bb + 0);
        float4 b1 = *reinterpret_cast<const float4*>(Bb + 4);
        float* dstA = sAs + 0 * TILE_F;
        float* dstB = sBs + 0 * TILE_F;
        dstA[(lcol + 0) * TROW + lrow] = a0.x;
        dstA[(lcol + 1) * TROW + lrow] = a0.y;
        dstA[(lcol + 2) * TROW + lrow] = a0.z;
        dstA[(lcol + 3) * TROW + lrow] = a0.w;
        dstA[(lcol + 4) * TROW + lrow] = a1.x;
        dstA[(lcol + 5) * TROW + lrow] = a1.y;
        dstA[(lcol + 6) * TROW + lrow] = a1.z;
        dstA[(lcol + 7) * TROW + lrow] = a1.w;
        dstB[(lcol + 0) * TROW + lrow] = b0.x;
        dstB[(lcol + 1) * TROW + lrow] = b0.y;
        dstB[(lcol + 2) * TROW + lrow] = b0.z;
        dstB[(lcol + 3) * TROW + lrow] = b0.w;
        dstB[(lcol + 4) * TROW + lrow] = b1.x;
        dstB[(lcol + 5) * TROW + lrow] = b1.y;
        dstB[(lcol + 6) * TROW + lrow] = b1.z;
        dstB[(lcol + 7) * TROW + lrow] = b1.w;
    }
    __syncthreads();

    int kcum = 0;
    for (int it = 0; it < NIT; it++) {
        const int buf = it & 1;
        const bool has_next = (it + 1) < NIT;

        // prefetch next tile (global -> regs), overlaps compute below
        float4 pa0, pa1, pb0, pb1;
        if (has_next) {
            const float* an = Ab + (size_t)(it + 1) * BK;
            const float* bn = Bb + (size_t)(it + 1) * BK;
            pa0 = *reinterpret_cast<const float4*>(an + 0);
            pa1 = *reinterpret_cast<const float4*>(an + 4);
            pb0 = *reinterpret_cast<const float4*>(bn + 0);
            pb1 = *reinterpret_cast<const float4*>(bn + 4);
        }

        const float* As = sAs + buf * TILE_F;
        const float* Bs = sBs + buf * TILE_F;

        // ---- sub-tile 0: k = 0..7 (ascending) ----
        #pragma unroll
        for (int k = 0; k < 8; k++) {
            float4 a0 = *reinterpret_cast<const float4*>(As + k * TROW + ty * 8);
            float4 a1 = *reinterpret_cast<const float4*>(As + k * TROW + ty * 8 + 4);
            float4 b0 = *reinterpret_cast<const float4*>(Bs + k * TROW + tx * 8);
            float4 b1 = *reinterpret_cast<const float4*>(Bs + k * TROW + tx * 8 + 4);
            float a[8] = {a0.x, a0.y, a0.z, a0.w, a1.x, a1.y, a1.z, a1.w};
            float b[8] = {b0.x, b0.y, b0.z, b0.w, b1.x, b1.y, b1.z, b1.w};
            #pragma unroll
            for (int i = 0; i < 8; i++)
                #pragma unroll
                for (int j = 0; j < 8; j++)
                    acc[i][j] = fmaf(a[i], b[j], acc[i][j]);
        }
        kcum += 8;
        if (kcum % KC == 0) {   // Eigen panel boundary: fold with separate add
            #pragma unroll
            for (int i = 0; i < 8; i++)
                #pragma unroll
                for (int j = 0; j < 8; j++) {
                    int idx = (i * 8 + j) * 256 + tid;
                    sTot[idx] = __fadd_rn(sTot[idx], acc[i][j]);
                    acc[i][j] = 0.0f;
                }
        }

        // ---- sub-tile 1: k = 8..15 ----
        #pragma unroll
        for (int k = 8; k < 16; k++) {
            float4 a0 = *reinterpret_cast<const float4*>(As + k * TROW + ty * 8);
            float4 a1 = *reinterpret_cast<const float4*>(As + k * TROW + ty * 8 + 4);
            float4 b0 = *reinterpret_cast<const float4*>(Bs + k * TROW + tx * 8);
            float4 b1 = *reinterpret_cast<const float4*>(Bs + k * TROW + tx * 8 + 4);
            float a[8] = {a0.x, a0.y, a0.z, a0.w, a1.x, a1.y, a1.z, a1.w};
            float b[8] = {b0.x, b0.y, b0.z, b0.w, b1.x, b1.y, b1.z, b1.w};
            #pragma unroll
            for (int i = 0; i < 8; i++)
                #pragma unroll
                for (int j = 0; j < 8; j++)
                    acc[i][j] = fmaf(a[i], b[j], acc[i][j]);
        }
        kcum += 8;
        if (kcum % KC == 0) {
            #pragma unroll
            for (int i = 0; i < 8; i++)
                #pragma unroll
                for (int j = 0; j < 8; j++) {
                    int idx = (i * 8 + j) * 256 + tid;
                    sTot[idx] = __fadd_rn(sTot[idx], acc[i][j]);
                    acc[i][j] = 0.0f;
                }
        }

        // store prefetched tile into other buffer
        if (has_next) {
            float* dstA = sAs + (buf ^ 1) * TILE_F;
            float* dstB = sBs + (buf ^ 1) * TILE_F;
            dstA[(lcol + 0) * TROW + lrow] = pa0.x;
            dstA[(lcol + 1) * TROW + lrow] = pa0.y;
            dstA[(lcol + 2) * TROW + lrow] = pa0.z;
            dstA[(lcol + 3) * TROW + lrow] = pa0.w;
            dstA[(lcol + 4) * TROW + lrow] = pa1.x;
            dstA[(lcol + 5) * TROW + lrow] = pa1.y;
            dstA[(lcol + 6) * TROW + lrow] = pa1.z;
            dstA[(lcol + 7) * TROW + lrow] = pa1.w;
            dstB[(lcol + 0) * TROW + lrow] = pb0.x;
            dstB[(lcol + 1) * TROW + lrow] = pb0.y;
            dstB[(lcol + 2) * TROW + lrow] = pb0.z;
            dstB[(lcol + 3) * TROW + lrow] = pb0.w;
            dstB[(lcol + 4) * TROW + lrow] = pb1.x;
            dstB[(lcol + 5) * TROW + lrow] = pb1.y;
            dstB[(lcol + 6) * TROW + lrow] = pb1.z;
            dstB[(lcol + 7) * TROW + lrow] = pb1.w;
        }
        __syncthreads();
    }

    // final fold: remainder panel (224 k) -> tot
    #pragma unroll
    for (int i = 0; i < 8; i++)
        #pragma unroll
        for (int j = 0; j < 8; j++) {
            int idx = (i * 8 + j) * 256 + tid;
            sTot[idx] = __fadd_rn(sTot[idx], acc[i][j]);
        }

    // writeout (each thread reads only its own tot column)
    #pragma unroll
    for (int i = 0; i < 8; i++) {
        int row = tile_m + ty * 8 + i;
        #pragma unroll
        for (int j = 0; j < 8; j++)
            C[(size_t)row * E + tile_n + tx * 8 + j] = sTot[(i * 8 + j) * 256 + tid];
    }
}

// ---------------------------------------------------------------------------
// XLA:CPU fused-loop sigmoid (FROZEN): 1/(1+exp(-x)), exp via VF32Exp with
// fused n = floor(fma(x, log2e, 0.5)).
// ---------------------------------------------------------------------------
__device__ __forceinline__ float vf32_exp(float x) {
    x = fminf(fmaxf(x, -87.8f), 88.8f);
    float fx = floorf(__fmaf_rn(x, 1.44269504088896341f, 0.5f));
    float tmp = __fmul_rn(fx, 0.693359375f);
    float z   = __fmul_rn(fx, -2.12194440e-4f);
    float r = __fsub_rn(__fsub_rn(x, tmp), z);
    float r2 = __fmul_rn(r, r);
    float y = 1.9875691500e-4f;
    y = __fmaf_rn(y, r, 1.3981999507e-3f);
    y = __fmaf_rn(y, r, 8.3334519073e-3f);
    y = __fmaf_rn(y, r, 4.1665795894e-2f);
    y = __fmaf_rn(y, r, 1.6666665459e-1f);
    y = __fmaf_rn(y, r, 5.0000001201e-1f);
    y = __fmaf_rn(y, r2, r);
    y = __fadd_rn(y, 1.0f);
    int n = (int)fx;
    return __fmul_rn(y, __int_as_float((n + 127) << 23));
}

__device__ __forceinline__ float xla_cpu_sigmoid(float x) {
    float e = vf32_exp(-x);
    return __fdiv_rn(1.0f, __fadd_rn(1.0f, e));
}

// ---------------------------------------------------------------------------
// Kernel 2: routing. One block (256 threads) per token. (FROZEN semantics)
// ---------------------------------------------------------------------------
__global__ __launch_bounds__(256) void router_topk(
    const float* __restrict__ logits,
    const float* __restrict__ bias,
    float* __restrict__ out_idx,
    float* __restrict__ out_w)
{
    __shared__ float s_score[NEXP];
    __shared__ float s_masked[NEXP];
    __shared__ float s_gscore[NGROUP];
    __shared__ int   s_gmask[NGROUP];
    __shared__ int   s_sel[TOPKN];

    const int t = blockIdx.x;
    const int e = threadIdx.x;
    const int warp = e >> 5, lane = e & 31;

    float logit = logits[(size_t)t * NEXP + e];
    float score = xla_cpu_sigmoid(logit);
    float corr = __fadd_rn(score, bias[e]);
    s_score[e] = score;

    // group top-2 sum (warp == group)
    float m1 = corr;
    #pragma unroll
    for (int o = 16; o > 0; o >>= 1)
        m1 = fmaxf(m1, __shfl_xor_sync(0xffffffffu, m1, o));
    unsigned ball = __ballot_sync(0xffffffffu, corr == m1);
    int firstlane = __ffs(ball) - 1;
    float v2 = (lane == firstlane) ? -INFINITY : corr;
    float m2 = v2;
    #pragma unroll
    for (int o = 16; o > 0; o >>= 1)
        m2 = fmaxf(m2, __shfl_xor_sync(0xffffffffu, m2, o));
    if (lane == 0) s_gscore[warp] = __fadd_rn(m1, m2);
    __syncthreads();

    // top-4 groups, stable (lowest index on ties)
    if (e == 0) {
        bool used[NGROUP];
        #pragma unroll
        for (int g = 0; g < NGROUP; g++) used[g] = false;
        for (int it = 0; it < TOPKG; it++) {
            float best = -INFINITY; int bi = 0;
            for (int g = 0; g < NGROUP; g++)
                if (!used[g] && s_gscore[g] > best) { best = s_gscore[g]; bi = g; }
            used[bi] = true;
        }
        #pragma unroll
        for (int g = 0; g < NGROUP; g++) s_gmask[g] = used[g] ? 1 : 0;
    }
    __syncthreads();

    s_masked[e] = s_gmask[warp] ? corr : 0.0f;
    __syncthreads();

    // top-8 over 256 (warp 0), stable
    if (warp == 0) {
        float lv[8];
        #pragma unroll
        for (int i = 0; i < 8; i++) lv[i] = s_masked[lane + i * 32];

        for (int it = 0; it < TOPKN; it++) {
            float best = -INFINITY; int bslot = 0;
            #pragma unroll
            for (int i = 0; i < 8; i++)
                if (lv[i] > best) { best = lv[i]; bslot = i; }
            int bidx = bslot * 32 + lane;
            #pragma unroll
            for (int o = 16; o > 0; o >>= 1) {
                float ov = __shfl_xor_sync(0xffffffffu, best, o);
                int   oi = __shfl_xor_sync(0xffffffffu, bidx, o);
                if (ov > best || (ov == best && oi < bidx)) { best = ov; bidx = oi; }
            }
            if (lane == 0) s_sel[it] = bidx;
            if (lane == (bidx & 31)) lv[bidx >> 5] = -INFINITY;
        }
        __syncwarp();

        float w = 0.0f;
        int myidx = 0;
        if (lane < TOPKN) {
            myidx = s_sel[lane];
            w = s_score[myidx];
        }
        float ws = w;
        #pragma unroll
        for (int o = 16; o > 0; o >>= 1)
            ws += __shfl_xor_sync(0xffffffffu, ws, o);
        if (lane < TOPKN) {
            float wn = __fmul_rn(__fdiv_rn(w, __fadd_rn(ws, 1e-20f)), 2.5f);
            out_idx[(size_t)t * TOPKN + lane] = (float)myidx;
            out_w[(size_t)t * TOPKN + lane] = wn;
        }
    }
}

// ---------------------------------------------------------------------------
extern "C" void kernel_launch(void* const* d_in, const int* in_sizes, int n_in,
                              void* d_out, int out_size) {
    const float* hidden = (const float*)d_in[0];
    const float* weight = (const float*)d_in[1];
    const float* bias   = (const float*)d_in[2];

    int E = in_sizes[2];
    int H = in_sizes[1] / E;
    int T = in_sizes[0] / H;

    float* logits = nullptr;
    cudaGetSymbolAddress((void**)&logits, g_logits);

    cudaFuncSetAttribute(router_gemm,
                         cudaFuncAttributeMaxDynamicSharedMemorySize, SM_TOTAL);

    dim3 gemm_grid(E / BN, T / BM);
    router_gemm<<<gemm_grid, 256, SM_TOTAL>>>(hidden, weight, logits, T, H, E);

    float* out = (float*)d_out;
    router_topk<<<T, 256>>>(logits, bias, out, out + (size_t)T * TOPKN);
}

// round 11
// speedup vs baseline: 2.2690x; 1.0419x over previous
#include <cuda_runtime.h>
#include <math.h>

#define TOKENS   16384
#define NEXP     256
#define HID      7168
#define NGROUP   8
#define TOPKG    4
#define TOPKN    8

// Scratch logits [T, E] (16 MB).
__device__ float g_logits[TOKENS * NEXP];

// ---------------------------------------------------------------------------
// Kernel 1: fp32 router GEMM, EIGEN-FAITHFUL ASSOCIATION (FROZEN NUMERICS):
//   per output: serial ascending-k fma chain within kc=248 panels,
//   C = ((0+S1)+S2)+... separate rn-adds at panel folds, remainder 224 last.
// Speed shape: BM=BN=128, BK=16, 256 threads, 8x8/thread, double-buffered.
// NEW: inner product uses packed fma.rn.f32x2 (FFMA2) — 2 output columns per
// lane-pair. Per-lane semantics identical to fmaf => bit-exact vs round 10.
// ---------------------------------------------------------------------------
#define BM 128
#define BN 128
#define BK 16
#define KC  248
#define TPAD 4
#define TROW (BM + TPAD)     // 132 floats; 528B rows (16B aligned)
#define TILE_F (BK * TROW)   // 2112 floats

#define SM_AS    0
#define SM_BS    (2 * TILE_F)
#define SM_TOT   (4 * TILE_F)                     // float offset; *4 % 8 == 0
#define SM_TOTAL ((4 * TILE_F) * 4 + 32 * 256 * 8)  // 33792 + 65536 = 99328 B

#define FMA2(acc, a, b) \
    asm("fma.rn.f32x2 %0, %1, %2, %0;" : "+l"(acc) : "l"(a), "l"(b))
#define ADD2(d, x, y) \
    asm("add.rn.f32x2 %0, %1, %2;" : "=l"(d) : "l"(x), "l"(y))
#define SPLAT2(p, f) \
    asm("mov.b64 %0, {%1, %1};" : "=l"(p) : "f"(f))
#define UNPK2(lo, hi, p) \
    asm("mov.b64 {%0, %1}, %2;" : "=f"(lo), "=f"(hi) : "l"(p))

__global__ __launch_bounds__(256, 2) void router_gemm(
    const float* __restrict__ A,   // [T, H]
    const float* __restrict__ B,   // [E, H]
    float* __restrict__ C,         // [T, E]
    int T, int H, int E)
{
    extern __shared__ float sm[];
    float* sAs = sm + SM_AS;
    float* sBs = sm + SM_BS;
    unsigned long long* sTot = reinterpret_cast<unsigned long long*>(sm + SM_TOT);

    const int tid = threadIdx.x;
    const int tx = tid & 15;
    const int ty = tid >> 4;
    const int tile_m = blockIdx.y * BM;
    const int tile_n = blockIdx.x * BN;

    const int lrow = tid >> 1;
    const int lcol = (tid & 1) * 8;

    const float* Ab = A + (size_t)(tile_m + lrow) * H + lcol;
    const float* Bb = B + (size_t)(tile_n + lrow) * H + lcol;

    #pragma unroll
    for (int i = 0; i < 32; i++) sTot[i * 256 + tid] = 0ull;

    // acc[i][jp]: packed pair = outputs (col 2jp, 2jp+1) for row i
    unsigned long long acc[8][4];
    #pragma unroll
    for (int i = 0; i < 8; i++)
        #pragma unroll
        for (int jp = 0; jp < 4; jp++) acc[i][jp] = 0ull;

    const int NIT = H / BK;   // 448

    // preload tile 0
    {
        float4 a0 = *reinterpret_cast<const float4*>(Ab + 0);
        float4 a1 = *reinterpret_cast<const float4*>(Ab + 4);
        float4 b0 = *reinterpret_cast<const float4*>(Bb + 0);
        float4 b1 = *reinterpret_cast<const float4*>(Bb + 4);
        float* dA = sAs;
        float* dB = sBs;
        dA[(lcol + 0) * TROW + lrow] = a0.x; dA[(lcol + 1) * TROW + lrow] = a0.y;
        dA[(lcol + 2) * TROW + lrow] = a0.z; dA[(lcol + 3) * TROW + lrow] = a0.w;
        dA[(lcol + 4) * TROW + lrow] = a1.x; dA[(lcol + 5) * TROW + lrow] = a1.y;
        dA[(lcol + 6) * TROW + lrow] = a1.z; dA[(lcol + 7) * TROW + lrow] = a1.w;
        dB[(lcol + 0) * TROW + lrow] = b0.x; dB[(lcol + 1) * TROW + lrow] = b0.y;
        dB[(lcol + 2) * TROW + lrow] = b0.z; dB[(lcol + 3) * TROW + lrow] = b0.w;
        dB[(lcol + 4) * TROW + lrow] = b1.x; dB[(lcol + 5) * TROW + lrow] = b1.y;
        dB[(lcol + 6) * TROW + lrow] = b1.z; dB[(lcol + 7) * TROW + lrow] = b1.w;
    }
    __syncthreads();

    int kcum = 0;
    for (int it = 0; it < NIT; it++) {
        const int buf = it & 1;
        const bool has_next = (it + 1) < NIT;

        float4 pa0, pa1, pb0, pb1;
        if (has_next) {
            const float* an = Ab + (size_t)(it + 1) * BK;
            const float* bn = Bb + (size_t)(it + 1) * BK;
            pa0 = *reinterpret_cast<const float4*>(an + 0);
            pa1 = *reinterpret_cast<const float4*>(an + 4);
            pb0 = *reinterpret_cast<const float4*>(bn + 0);
            pb1 = *reinterpret_cast<const float4*>(bn + 4);
        }

        const float* As = sAs + buf * TILE_F;
        const float* Bs = sBs + buf * TILE_F;

        #pragma unroll
        for (int half = 0; half < 2; half++) {
            #pragma unroll
            for (int kk = 0; kk < 8; kk++) {
                const int k = half * 8 + kk;
                // B pairs straight from 16B smem loads
                ulonglong2 bp0 = *reinterpret_cast<const ulonglong2*>(Bs + k * TROW + tx * 8);
                ulonglong2 bp1 = *reinterpret_cast<const ulonglong2*>(Bs + k * TROW + tx * 8 + 4);
                unsigned long long bq[4] = {bp0.x, bp0.y, bp1.x, bp1.y};
                // A values + lane splats
                float4 a0 = *reinterpret_cast<const float4*>(As + k * TROW + ty * 8);
                float4 a1 = *reinterpret_cast<const float4*>(As + k * TROW + ty * 8 + 4);
                float av[8] = {a0.x, a0.y, a0.z, a0.w, a1.x, a1.y, a1.z, a1.w};
                #pragma unroll
                for (int i = 0; i < 8; i++) {
                    unsigned long long ap;
                    SPLAT2(ap, av[i]);
                    FMA2(acc[i][0], ap, bq[0]);
                    FMA2(acc[i][1], ap, bq[1]);
                    FMA2(acc[i][2], ap, bq[2]);
                    FMA2(acc[i][3], ap, bq[3]);
                }
            }
            kcum += 8;
            if (kcum % KC == 0) {   // Eigen panel fold: per-lane rn add
                #pragma unroll
                for (int i = 0; i < 8; i++)
                    #pragma unroll
                    for (int jp = 0; jp < 4; jp++) {
                        int idx = (i * 4 + jp) * 256 + tid;
                        unsigned long long tot = sTot[idx];
                        ADD2(tot, tot, acc[i][jp]);
                        sTot[idx] = tot;
                        acc[i][jp] = 0ull;
                    }
            }
        }

        if (has_next) {
            float* dA = sAs + (buf ^ 1) * TILE_F;
            float* dB = sBs + (buf ^ 1) * TILE_F;
            dA[(lcol + 0) * TROW + lrow] = pa0.x; dA[(lcol + 1) * TROW + lrow] = pa0.y;
            dA[(lcol + 2) * TROW + lrow] = pa0.z; dA[(lcol + 3) * TROW + lrow] = pa0.w;
            dA[(lcol + 4) * TROW + lrow] = pa1.x; dA[(lcol + 5) * TROW + lrow] = pa1.y;
            dA[(lcol + 6) * TROW + lrow] = pa1.z; dA[(lcol + 7) * TROW + lrow] = pa1.w;
            dB[(lcol + 0) * TROW + lrow] = pb0.x; dB[(lcol + 1) * TROW + lrow] = pb0.y;
            dB[(lcol + 2) * TROW + lrow] = pb0.z; dB[(lcol + 3) * TROW + lrow] = pb0.w;
            dB[(lcol + 4) * TROW + lrow] = pb1.x; dB[(lcol + 5) * TROW + lrow] = pb1.y;
            dB[(lcol + 6) * TROW + lrow] = pb1.z; dB[(lcol + 7) * TROW + lrow] = pb1.w;
        }
        __syncthreads();
    }

    // remainder panel (224 k)
    #pragma unroll
    for (int i = 0; i < 8; i++)
        #pragma unroll
        for (int jp = 0; jp < 4; jp++) {
            int idx = (i * 4 + jp) * 256 + tid;
            unsigned long long tot = sTot[idx];
            ADD2(tot, tot, acc[i][jp]);
            sTot[idx] = tot;
        }

    // writeout
    #pragma unroll
    for (int i = 0; i < 8; i++) {
        int row = tile_m + ty * 8 + i;
        #pragma unroll
        for (int jp = 0; jp < 4; jp++) {
            float lo, hi;
            UNPK2(lo, hi, sTot[(i * 4 + jp) * 256 + tid]);
            C[(size_t)row * E + tile_n + tx * 8 + 2 * jp + 0] = lo;
            C[(size_t)row * E + tile_n + tx * 8 + 2 * jp + 1] = hi;
        }
    }
}

// ---------------------------------------------------------------------------
// XLA:CPU fused-loop sigmoid (FROZEN): 1/(1+exp(-x)), exp via VF32Exp with
// fused n = floor(fma(x, log2e, 0.5)).
// ---------------------------------------------------------------------------
__device__ __forceinline__ float vf32_exp(float x) {
    x = fminf(fmaxf(x, -87.8f), 88.8f);
    float fx = floorf(__fmaf_rn(x, 1.44269504088896341f, 0.5f));
    float tmp = __fmul_rn(fx, 0.693359375f);
    float z   = __fmul_rn(fx, -2.12194440e-4f);
    float r = __fsub_rn(__fsub_rn(x, tmp), z);
    float r2 = __fmul_rn(r, r);
    float y = 1.9875691500e-4f;
    y = __fmaf_rn(y, r, 1.3981999507e-3f);
    y = __fmaf_rn(y, r, 8.3334519073e-3f);
    y = __fmaf_rn(y, r, 4.1665795894e-2f);
    y = __fmaf_rn(y, r, 1.6666665459e-1f);
    y = __fmaf_rn(y, r, 5.0000001201e-1f);
    y = __fmaf_rn(y, r2, r);
    y = __fadd_rn(y, 1.0f);
    int n = (int)fx;
    return __fmul_rn(y, __int_as_float((n + 127) << 23));
}

__device__ __forceinline__ float xla_cpu_sigmoid(float x) {
    float e = vf32_exp(-x);
    return __fdiv_rn(1.0f, __fadd_rn(1.0f, e));
}

// ---------------------------------------------------------------------------
// Kernel 2: routing. One block (256 threads) per token. (FROZEN semantics)
// ---------------------------------------------------------------------------
__global__ __launch_bounds__(256) void router_topk(
    const float* __restrict__ logits,
    const float* __restrict__ bias,
    float* __restrict__ out_idx,
    float* __restrict__ out_w)
{
    __shared__ float s_score[NEXP];
    __shared__ float s_masked[NEXP];
    __shared__ float s_gscore[NGROUP];
    __shared__ int   s_gmask[NGROUP];
    __shared__ int   s_sel[TOPKN];

    const int t = blockIdx.x;
    const int e = threadIdx.x;
    const int warp = e >> 5, lane = e & 31;

    float logit = logits[(size_t)t * NEXP + e];
    float score = xla_cpu_sigmoid(logit);
    float corr = __fadd_rn(score, bias[e]);
    s_score[e] = score;

    float m1 = corr;
    #pragma unroll
    for (int o = 16; o > 0; o >>= 1)
        m1 = fmaxf(m1, __shfl_xor_sync(0xffffffffu, m1, o));
    unsigned ball = __ballot_sync(0xffffffffu, corr == m1);
    int firstlane = __ffs(ball) - 1;
    float v2 = (lane == firstlane) ? -INFINITY : corr;
    float m2 = v2;
    #pragma unroll
    for (int o = 16; o > 0; o >>= 1)
        m2 = fmaxf(m2, __shfl_xor_sync(0xffffffffu, m2, o));
    if (lane == 0) s_gscore[warp] = __fadd_rn(m1, m2);
    __syncthreads();

    if (e == 0) {
        bool used[NGROUP];
        #pragma unroll
        for (int g = 0; g < NGROUP; g++) used[g] = false;
        for (int it = 0; it < TOPKG; it++) {
            float best = -INFINITY; int bi = 0;
            for (int g = 0; g < NGROUP; g++)
                if (!used[g] && s_gscore[g] > best) { best = s_gscore[g]; bi = g; }
            used[bi] = true;
        }
        #pragma unroll
        for (int g = 0; g < NGROUP; g++) s_gmask[g] = used[g] ? 1 : 0;
    }
    __syncthreads();

    s_masked[e] = s_gmask[warp] ? corr : 0.0f;
    __syncthreads();

    if (warp == 0) {
        float lv[8];
        #pragma unroll
        for (int i = 0; i < 8; i++) lv[i] = s_masked[lane + i * 32];

        for (int it = 0; it < TOPKN; it++) {
            float best = -INFINITY; int bslot = 0;
            #pragma unroll
            for (int i = 0; i < 8; i++)
                if (lv[i] > best) { best = lv[i]; bslot = i; }
            int bidx = bslot * 32 + lane;
            #pragma unroll
            for (int o = 16; o > 0; o >>= 1) {
                float ov = __shfl_xor_sync(0xffffffffu, best, o);
                int   oi = __shfl_xor_sync(0xffffffffu, bidx, o);
                if (ov > best || (ov == best && oi < bidx)) { best = ov; bidx = oi; }
            }
            if (lane == 0) s_sel[it] = bidx;
            if (lane == (bidx & 31)) lv[bidx >> 5] = -INFINITY;
        }
        __syncwarp();

        float w = 0.0f;
        int myidx = 0;
        if (lane < TOPKN) {
            myidx = s_sel[lane];
            w = s_score[myidx];
        }
        float ws = w;
        #pragma unroll
        for (int o = 16; o > 0; o >>= 1)
            ws += __shfl_xor_sync(0xffffffffu, ws, o);
        if (lane < TOPKN) {
            float wn = __fmul_rn(__fdiv_rn(w, __fadd_rn(ws, 1e-20f)), 2.5f);
            out_idx[(size_t)t * TOPKN + lane] = (float)myidx;
            out_w[(size_t)t * TOPKN + lane] = wn;
        }
    }
}

// ---------------------------------------------------------------------------
extern "C" void kernel_launch(void* const* d_in, const int* in_sizes, int n_in,
                              void* d_out, int out_size) {
    const float* hidden = (const float*)d_in[0];
    const float* weight = (const float*)d_in[1];
    const float* bias   = (const float*)d_in[2];

    int E = in_sizes[2];
    int H = in_sizes[1] / E;
    int T = in_sizes[0] / H;

    float* logits = nullptr;
    cudaGetSymbolAddress((void**)&logits, g_logits);

    cudaFuncSetAttribute(router_gemm,
                         cudaFuncAttributeMaxDynamicSharedMemorySize, SM_TOTAL);

    dim3 gemm_grid(E / BN, T / BM);
    router_gemm<<<gemm_grid, 256, SM_TOTAL>>>(hidden, weight, logits, T, H, E);

    float* out = (float*)d_out;
    router_topk<<<T, 256>>>(logits, bias, out, out + (size_t)T * TOPKN);
}